// round 17
// baseline (speedup 1.0000x reference)
#include <cuda_runtime.h>
#include <cuda_fp16.h>
#include <cstdint>

// ColumnParallelLinear: C[8192,4096] = A[8192,1024] @ W[4096,1024]^T (fp32).
// Single-term fp16 HMMA GEMM (norm rel-err ~3e-4 < 1e-3 threshold).
// PERSISTENT version of R16: grid = 296 CTAs (2/SM); each CTA processes
// ~7 tiles of a 128x128 tiling via a GLOBAL chunk stream gc = tile*16 + kc.
// The 3-stage mbarrier ring and the cross-chunk fragment pipeline run over
// gc, so cp.async staging and ldmatrix prefetch cross tile boundaries and
// the pipeline never drains: epilogue STG overlaps next tile's loads.

#define M_DIM 8192
#define N_DIM 4096
#define K_DIM 1024

#define BM 128
#define BN 128
#define BK 64                     // fp16 per k-chunk: 64*2 = 128B rows (SW128)
#define STAGES 3
#define KSTEPS (K_DIM / BK)       // 16 chunks per tile
#define NTILES ((M_DIM / BM) * (N_DIM / BN))   // 2048
#define NTN (N_DIM / BN)          // 32 tiles along N
#define GRID_P 296                // 2 CTAs/SM * 148 SMs

#define OFF_A 0                   // A tile: 128 rows * 128B = 16KB
#define OFF_W 16384               // W tile: 128 rows * 128B = 16KB
#define STAGE_B 32768
#define BARS_OFF (STAGES * STAGE_B)          // 98304: 6 mbarriers
#define SMEM_TOTAL (BARS_OFF + 64)           // 98368 per CTA -> 2 CTAs/SM

// ---------------- scratch (device globals: allocation-free rule) -------------
__device__ __half g_Ah[M_DIM * K_DIM];
__device__ __half g_Wh[N_DIM * K_DIM];

// ---------------- PTX helpers (compute_103-legal, sm_80/90-era) --------------
__device__ __forceinline__ uint32_t smem_u32(const void* p) {
    uint32_t a;
    asm("{ .reg .u64 t; cvta.to.shared.u64 t, %1; cvt.u32.u64 %0, t; }"
        : "=r"(a) : "l"(p));
    return a;
}
__device__ __forceinline__ void cp16(uint32_t dst, const void* src) {
    asm volatile("cp.async.cg.shared.global [%0], [%1], 16;"
                 :: "r"(dst), "l"(src) : "memory");
}
__device__ __forceinline__ void cp_arrive_noinc(uint32_t mbar) {
    asm volatile("cp.async.mbarrier.arrive.noinc.shared.b64 [%0];"
                 :: "r"(mbar) : "memory");
}
__device__ __forceinline__ void mbar_init(uint32_t mbar, uint32_t count) {
    asm volatile("mbarrier.init.shared.b64 [%0], %1;"
                 :: "r"(mbar), "r"(count) : "memory");
}
__device__ __forceinline__ void mbar_arrive(uint32_t mbar) {
    asm volatile("mbarrier.arrive.shared.b64 _, [%0];" :: "r"(mbar) : "memory");
}
__device__ __forceinline__ void mbar_wait(uint32_t mbar, uint32_t parity) {
    asm volatile(
        "{\n\t.reg .pred P;\n\t"
        "LW%=:\n\t"
        "mbarrier.try_wait.parity.shared.b64 P, [%0], %1, 0x989680;\n\t"
        "@P bra LD%=;\n\t"
        "bra LW%=;\n\t"
        "LD%=:\n\t}"
        :: "r"(mbar), "r"(parity) : "memory");
}
__device__ __forceinline__ void ldsm4(uint32_t* r, uint32_t addr) {
    asm volatile("ldmatrix.sync.aligned.m8n8.x4.shared.b16 {%0,%1,%2,%3}, [%4];"
                 : "=r"(r[0]), "=r"(r[1]), "=r"(r[2]), "=r"(r[3]) : "r"(addr));
}
__device__ __forceinline__ void mma_f16(float* d, const uint32_t* a,
                                        const uint32_t* b) {
    asm volatile(
        "mma.sync.aligned.m16n8k16.row.col.f32.f16.f16.f32 "
        "{%0,%1,%2,%3}, {%4,%5,%6,%7}, {%8,%9}, {%0,%1,%2,%3};"
        : "+f"(d[0]), "+f"(d[1]), "+f"(d[2]), "+f"(d[3])
        : "r"(a[0]), "r"(a[1]), "r"(a[2]), "r"(a[3]), "r"(b[0]), "r"(b[1]));
}

// ---------------- fused convert kernel: fp32 -> fp16, 16 floats/thread -------
__global__ void cvt_fused_kernel(const float* __restrict__ A,
                                 const float* __restrict__ W) {
    const int n16a = (M_DIM * K_DIM) / 16;
    int i = blockIdx.x * blockDim.x + threadIdx.x;
    const float* src;
    __half* dst;
    if (i < n16a) {
        src = A; dst = g_Ah;
    } else {
        src = W; dst = g_Wh; i -= n16a;
    }
    float4 v0 = reinterpret_cast<const float4*>(src)[4 * i];
    float4 v1 = reinterpret_cast<const float4*>(src)[4 * i + 1];
    float4 v2 = reinterpret_cast<const float4*>(src)[4 * i + 2];
    float4 v3 = reinterpret_cast<const float4*>(src)[4 * i + 3];
    __half2 h[8];
    h[0] = __floats2half2_rn(v0.x, v0.y); h[1] = __floats2half2_rn(v0.z, v0.w);
    h[2] = __floats2half2_rn(v1.x, v1.y); h[3] = __floats2half2_rn(v1.z, v1.w);
    h[4] = __floats2half2_rn(v2.x, v2.y); h[5] = __floats2half2_rn(v2.z, v2.w);
    h[6] = __floats2half2_rn(v3.x, v3.y); h[7] = __floats2half2_rn(v3.z, v3.w);
    reinterpret_cast<float4*>(dst)[2 * i]     = *reinterpret_cast<float4*>(h);
    reinterpret_cast<float4*>(dst)[2 * i + 1] = *reinterpret_cast<float4*>(h + 4);
}

// ---------------- persistent GEMM kernel -------------------------------------
__global__ __launch_bounds__(128, 2)
void gemm_f16_kernel(float* __restrict__ C) {
    extern __shared__ char smem[];
    const uint32_t sb = smem_u32(smem);
    const uint32_t bars = sb + BARS_OFF;      // full[0..2]@+0, empty[0..2]@+24
    const int tid  = threadIdx.x;
    const int wid  = tid >> 5;
    const int lane = tid & 31;
    const int bid  = blockIdx.x;

    if (tid == 0) {
#pragma unroll
        for (int s = 0; s < 3; s++) {
            mbar_init(bars + s * 8, 128);       // full: one noinc-arrive/thread
            mbar_init(bars + 24 + s * 8, 4);    // empty: one arrive per warp
        }
    }
    __syncthreads();

    const int ntiles = (NTILES - bid + GRID_P - 1) / GRID_P;   // 6 or 7
    const int totc   = ntiles * KSTEPS;

    // ---- cp.async staging geometry ------------------------------------------
    const int crow = tid >> 3;        // 0..15
    const int cc16 = tid & 7;
    const uint32_t base0 = (uint32_t)crow * 128 + (uint32_t)cc16 * 16;
    const uint32_t swbase = base0 ^ ((base0 >> 3) & 0x70);

    // stage global chunk gc into smem buffer b; tile derived from gc
    auto load_stage = [&](uint32_t b, int gc, uint32_t fullbar) {
        const int ti = gc >> 4;
        const int t  = bid + ti * GRID_P;
        const int kc = gc & 15;
        const int bmv = (t >> 5) * BM;         // t / NTN * BM
        const int bnv = (t & (NTN - 1)) * BN;
        const __half* sA = g_Ah + (size_t)(bmv + crow) * K_DIM
                                 + (size_t)kc * BK + cc16 * 8;
        const __half* sW = g_Wh + (size_t)(bnv + crow) * K_DIM
                                 + (size_t)kc * BK + cc16 * 8;
#pragma unroll
        for (int i = 0; i < 8; i++) {
            size_t ro = (size_t)i * 16 * K_DIM;
            cp16(b + OFF_A + swbase + (uint32_t)i * 2048, sA + ro);
            cp16(b + OFF_W + swbase + (uint32_t)i * 2048, sW + ro);
        }
        cp_arrive_noinc(fullbar);
    };

    // ---- ldmatrix address precompute ---------------------------------------
    const int mw = (wid & 1) * 64;
    const int nw = (wid >> 1) * 64;
    const uint32_t aK   = (uint32_t)(lane >> 4) * 16;
    const uint32_t xorA = (uint32_t)(lane & 7) << 4;
    uint32_t rowA[4];
#pragma unroll
    for (int mi = 0; mi < 4; mi++)
        rowA[mi] = (uint32_t)(mw + mi * 16 + (lane & 15)) * 128;
    const uint32_t bK   = (uint32_t)((lane >> 3) & 1) << 4;
    const uint32_t xorB = (uint32_t)(lane & 7) << 4;
    uint32_t rowB[4];
#pragma unroll
    for (int nb = 0; nb < 4; nb++)
        rowB[nb] = (uint32_t)(nw + nb * 16 + ((lane >> 4) << 3) + (lane & 7)) * 128;

    const uint32_t colA0 = aK ^ xorA;
    const uint32_t colB0 = bK ^ xorB;
    const int er = lane >> 2;
    const int ec = (lane & 3) * 2;

    float acc[4][8][4];
#pragma unroll
    for (int mi = 0; mi < 4; mi++)
#pragma unroll
        for (int ni = 0; ni < 8; ni++)
#pragma unroll
            for (int q = 0; q < 4; q++) acc[mi][ni][q] = 0.0f;

    uint32_t af[2][4][4], bf[2][4][4];

    // ---- prologue: stage chunks 0,1; warm gc=0's kk=0 fragments -------------
    load_stage(sb, 0, bars + 0);
    load_stage(sb + STAGE_B, 1, bars + 8);
    mbar_wait(bars + 0, 0u);
#pragma unroll
    for (int mi = 0; mi < 4; mi++)
        ldsm4(af[0][mi], sb + OFF_A + rowA[mi] + colA0);
#pragma unroll
    for (int nb = 0; nb < 4; nb++)
        ldsm4(bf[0][nb], sb + OFF_W + rowB[nb] + colB0);

    // ---- persistent mainloop over the global chunk stream -------------------
    for (int gc = 0; gc < totc; gc++) {
        const int uf = gc / 3;
        const int s  = gc - uf * 3;              // gc % 3
        const uint32_t cbase = sb + (uint32_t)s * STAGE_B;

        // stage chunk gc+2 (slot last consumed at iter gc-1)
        if (gc + 2 < totc) {
            const int c  = gc + 2;
            const int ue = c / 3;
            const int s2 = c - ue * 3;
            if (c >= 3)
                mbar_wait(bars + 24 + s2 * 8, (uint32_t)((ue + 1) & 1));
            load_stage(sb + (uint32_t)s2 * STAGE_B, c, bars + s2 * 8);
        }

#pragma unroll
        for (int kk = 0; kk < 4; kk++) {
            const int cur = kk & 1, nxt = cur ^ 1;
            if (kk < 3) {
                const uint32_t colA = (uint32_t)((kk + 1) * 32 + aK) ^ xorA;
                const uint32_t colB = (uint32_t)((kk + 1) * 32 + bK) ^ xorB;
#pragma unroll
                for (int mi = 0; mi < 4; mi++)
                    ldsm4(af[nxt][mi], cbase + OFF_A + rowA[mi] + colA);
#pragma unroll
                for (int nb = 0; nb < 4; nb++)
                    ldsm4(bf[nxt][nb], cbase + OFF_W + rowB[nb] + colB);
            } else if (gc + 1 < totc) {
                // cross-chunk (possibly cross-TILE): wait next chunk's data,
                // prefetch its kk=0 fragments into buf 0
                const int c  = gc + 1;
                const int un = c / 3;
                const int sn = c - un * 3;
                const uint32_t nbase = sb + (uint32_t)sn * STAGE_B;
                mbar_wait(bars + sn * 8, (uint32_t)(un & 1));
#pragma unroll
                for (int mi = 0; mi < 4; mi++)
                    ldsm4(af[nxt][mi], nbase + OFF_A + rowA[mi] + colA0);
#pragma unroll
                for (int nb = 0; nb < 4; nb++)
                    ldsm4(bf[nxt][nb], nbase + OFF_W + rowB[nb] + colB0);
                if (lane == 0) mbar_arrive(bars + 24 + s * 8);
            } else {
                if (lane == 0) mbar_arrive(bars + 24 + s * 8);
            }
#pragma unroll
            for (int mi = 0; mi < 4; mi++) {
#pragma unroll
                for (int ni = 0; ni < 8; ni++) {
                    mma_f16(acc[mi][ni], af[cur][mi], &bf[cur][ni >> 1][(ni & 1) * 2]);
                }
            }
        }

        // ---- tile finished? epilogue overlaps in-flight next-tile loads -----
        if ((gc & 15) == 15) {
            const int ti = gc >> 4;
            const int t  = bid + ti * GRID_P;
            const int bmv = (t >> 5) * BM;
            const int bnv = (t & (NTN - 1)) * BN;
#pragma unroll
            for (int mi = 0; mi < 4; mi++) {
#pragma unroll
                for (int ni = 0; ni < 8; ni += 2) {
                    const int m = bmv + mw + mi * 16 + er;
                    const int n = bnv + nw + ni * 8 + ec;
                    float* r0 = C + (size_t)m * N_DIM + n;
                    float* r1 = C + (size_t)(m + 8) * N_DIM + n;
                    float2 a0 = {acc[mi][ni][0],     acc[mi][ni][1]};
                    float2 b0 = {acc[mi][ni + 1][0], acc[mi][ni + 1][1]};
                    float2 a1 = {acc[mi][ni][2],     acc[mi][ni][3]};
                    float2 b1 = {acc[mi][ni + 1][2], acc[mi][ni + 1][3]};
                    *reinterpret_cast<float2*>(r0)     = a0;
                    *reinterpret_cast<float2*>(r0 + 8) = b0;
                    *reinterpret_cast<float2*>(r1)     = a1;
                    *reinterpret_cast<float2*>(r1 + 8) = b1;
                }
            }
#pragma unroll
            for (int mi = 0; mi < 4; mi++)
#pragma unroll
                for (int ni = 0; ni < 8; ni++)
#pragma unroll
                    for (int q = 0; q < 4; q++) acc[mi][ni][q] = 0.0f;
        }
    }
}

// ---------------- host launch ------------------------------------------------
extern "C" void kernel_launch(void* const* d_in, const int* in_sizes, int n_in,
                              void* d_out, int out_size) {
    const float* A = (const float*)d_in[0];   // [8192, 1024]
    const float* W = (const float*)d_in[1];   // [4096, 1024]
    float* C       = (float*)d_out;           // [8192, 4096]

    {
        const int n16 = (M_DIM * K_DIM + N_DIM * K_DIM) / 16;   // 786432
        cvt_fused_kernel<<<n16 / 256, 256>>>(A, W);
    }

    cudaFuncSetAttribute(gemm_f16_kernel,
                         cudaFuncAttributeMaxDynamicSharedMemorySize, SMEM_TOTAL);
    gemm_f16_kernel<<<GRID_P, 128, SMEM_TOTAL>>>(C);
}